// round 12
// baseline (speedup 1.0000x reference)
#include <cuda_runtime.h>
#include <cuda_bf16.h>
#include <math.h>

#define H       128
#define PTS     32      // interior points per tile (M = 4*PTS = 128 rows)
#define TB      32      // boundary points per block
#define THREADS_I 512
#define THREADS 256
#define NBLK    148

typedef unsigned int u32;

// Per-block partial sums (deterministic two-stage reduction; no device mallocs)
__device__ float g_part_int[65536];
__device__ float g_part_bd[8192];

// Accurate tanh independent of -use_fast_math lowering of tanhf.
__device__ __forceinline__ float my_tanh(float x)
{
    float ax = fabsf(x);
    float t  = __expf(-2.0f * ax);
    float r  = (1.0f - t) / (1.0f + t);
    return copysignf(r, x);
}

// ---------------- smem layout (bytes from dynamic base) ----------------
// bf16 tiles: 128 rows x 128 cols, 256 B/row, XOR-swizzled 16B chunks.
#define SM_AHI   0
#define SM_ALO   32768
#define SM_W1HI  65536
#define SM_W1LO  98304
#define SM_W2HI  131072
#define SM_W2LO  163840
#define SM_SLAP  196608                 // 64 floats
#define SMEM_TOTAL (SM_SLAP + 256)      // 196864 B

// swizzled byte offset inside a bf16 tile: 16B chunk index ^= (row & 7)
__device__ __forceinline__ u32 toff(int row, int col)
{
    return (u32)(row * 256 + ((((col >> 3) ^ (row & 7)) << 4)) + (col & 7) * 2);
}

__device__ __forceinline__ u32 smem_to_u32(const void* p)
{
    u32 a;
    asm("{ .reg .u64 t; cvta.to.shared.u64 t, %1; cvt.u32.u64 %0, t; }"
        : "=r"(a) : "l"(p));
    return a;
}

__device__ __forceinline__ void ldsm4(u32* r, u32 addr)
{
    asm volatile("ldmatrix.sync.aligned.m8n8.x4.shared.b16 {%0,%1,%2,%3}, [%4];"
                 : "=r"(r[0]), "=r"(r[1]), "=r"(r[2]), "=r"(r[3]) : "r"(addr));
}

__device__ __forceinline__ void mma_bf16(float* c, const u32* a, u32 b0, u32 b1)
{
    asm volatile(
        "mma.sync.aligned.m16n8k16.row.col.f32.bf16.bf16.f32 "
        "{%0,%1,%2,%3}, {%4,%5,%6,%7}, {%8,%9}, {%0,%1,%2,%3};"
        : "+f"(c[0]), "+f"(c[1]), "+f"(c[2]), "+f"(c[3])
        : "r"(a[0]), "r"(a[1]), "r"(a[2]), "r"(a[3]), "r"(b0), "r"(b1));
}

__device__ __forceinline__ u32 pack2bf(float a, float b)
{
    return ((u32)__bfloat16_as_ushort(__float2bfloat16(b)) << 16)
         |  (u32)__bfloat16_as_ushort(__float2bfloat16(a));
}

// ---------------------------------------------------------------------------
// 3-term bf16-split GEMM mainloop. Warp (wm, wn): rows 16wm..16wm+15,
// cols 64wn..64wn+63; acc[8][4].  D += Ahi*Bhi + Ahi*Blo + Alo*Bhi.
// ---------------------------------------------------------------------------
__device__ __forceinline__ void mainloop(u32 smb, u32 ahi, u32 alo,
                                         u32 whi, u32 wlo,
                                         int lane, int wm, int wn,
                                         float acc[8][4])
{
#pragma unroll
    for (int i = 0; i < 8; i++)
#pragma unroll
        for (int j = 0; j < 4; j++) acc[i][j] = 0.0f;

    const int arow = wm * 16 + (lane & 15);
    const int ahi4 = lane >> 4;               // 0/1 -> k +8
    const int brl  = ((lane >> 4) & 1) * 8 + (lane & 7);
    const int bko  = (lane >> 3) & 1;         // 0/1 -> k chunk +1

#pragma unroll 2
    for (int s = 0; s < 8; s++) {
        u32 aoffs = (u32)(arow * 256 + (((s * 2 + ahi4) ^ (arow & 7)) << 4));
        u32 ah[4], al[4];
        ldsm4(ah, smb + ahi + aoffs);
        ldsm4(al, smb + alo + aoffs);

        u32 bh[16], bl[16];
#pragma unroll
        for (int jp = 0; jp < 4; jp++) {
            int brow = wn * 64 + jp * 16 + brl;
            u32 boffs = (u32)(brow * 256 + (((s * 2 + bko) ^ (brow & 7)) << 4));
            ldsm4(&bh[jp * 4], smb + whi + boffs);
            ldsm4(&bl[jp * 4], smb + wlo + boffs);
        }

#pragma unroll
        for (int jp = 0; jp < 4; jp++) {      // hi * hi
            mma_bf16(acc[2 * jp],     ah, bh[4 * jp],     bh[4 * jp + 1]);
            mma_bf16(acc[2 * jp + 1], ah, bh[4 * jp + 2], bh[4 * jp + 3]);
        }
#pragma unroll
        for (int jp = 0; jp < 4; jp++) {      // hi * lo
            mma_bf16(acc[2 * jp],     ah, bl[4 * jp],     bl[4 * jp + 1]);
            mma_bf16(acc[2 * jp + 1], ah, bl[4 * jp + 2], bl[4 * jp + 3]);
        }
#pragma unroll
        for (int jp = 0; jp < 4; jp++) {      // lo * hi
            mma_bf16(acc[2 * jp],     al, bh[4 * jp],     bh[4 * jp + 1]);
            mma_bf16(acc[2 * jp + 1], al, bh[4 * jp + 2], bh[4 * jp + 3]);
        }
    }
}

// ---------------------------------------------------------------------------
// In-register hidden epilogue. Fragment rows are 4p+c; channel of this
// thread's rows: c = (lane>>2)&3. Gather zv/zgx/zgy from lanes src, src+4,
// src+8 (validated fragment layout: c0=(g,2q), c1=(g,2q+1), c2/c3=row g+8).
// Writes new bf16 hi/lo A tiles directly (swizzled STS.32).
// ---------------------------------------------------------------------------
__device__ __forceinline__ void epi_hidden(char* sm,
                                           const float* __restrict__ b,
                                           int lane, int wm, int wn,
                                           const float acc[8][4])
{
    const int g   = lane >> 2, q = lane & 3;
    const int c   = g & 3;
    const int src = lane - 4 * c;
    const u32 FM  = 0xffffffffu;

#pragma unroll
    for (int nt = 0; nt < 8; nt++) {
        const int colg = wn * 64 + nt * 8 + q * 2;
        const float b0v = __ldg(&b[colg]);
        const float b1v = __ldg(&b[colg + 1]);
        float out[4];
#pragma unroll
        for (int e = 0; e < 4; e++) {
            float dv = acc[nt][e];
            float zv = __shfl_sync(FM, dv, src);
            float gx = __shfl_sync(FM, dv, src + 4);
            float gy = __shfl_sync(FM, dv, src + 8);
            float a  = my_tanh(zv + ((e & 1) ? b1v : b0v));
            float t1 = 1.0f - a * a;
            float t2 = -2.0f * a * t1;
            float o;
            if (c == 0)      o = a;
            else if (c == 3) o = fmaf(t2, fmaf(gx, gx, gy * gy), t1 * dv);
            else             o = t1 * dv;
            out[e] = o;
        }
        const int r0 = wm * 16 + g;
        const u32 off0 = toff(r0, colg);
        const u32 off1 = toff(r0 + 8, colg);
        float h0 = __bfloat162float(__float2bfloat16(out[0]));
        float h1 = __bfloat162float(__float2bfloat16(out[1]));
        float h2 = __bfloat162float(__float2bfloat16(out[2]));
        float h3 = __bfloat162float(__float2bfloat16(out[3]));
        *(u32*)(sm + SM_AHI + off0) = pack2bf(out[0], out[1]);
        *(u32*)(sm + SM_ALO + off0) = pack2bf(out[0] - h0, out[1] - h1);
        *(u32*)(sm + SM_AHI + off1) = pack2bf(out[2], out[3]);
        *(u32*)(sm + SM_ALO + off1) = pack2bf(out[2] - h2, out[3] - h3);
    }
}

// ---------------------------------------------------------------------------
// In-register output epilogue: lap(p) partial = sum_cols L * W3.
// Only c==3 lanes produce valid L; reduce over q via shfl_xor.
// ---------------------------------------------------------------------------
__device__ __forceinline__ void epi_out(float* SLAP,
                                        const float* __restrict__ b2,
                                        const float* __restrict__ W3,
                                        int lane, int wm, int wn,
                                        const float acc[8][4])
{
    const int g   = lane >> 2, q = lane & 3;
    const int c   = g & 3;
    const int src = lane - 4 * c;
    const u32 FM  = 0xffffffffu;

    float s0 = 0.0f, s1 = 0.0f;
#pragma unroll
    for (int nt = 0; nt < 8; nt++) {
        const int colg = wn * 64 + nt * 8 + q * 2;
        const float b0v = __ldg(&b2[colg]);
        const float b1v = __ldg(&b2[colg + 1]);
        const float w0v = __ldg(&W3[colg]);
        const float w1v = __ldg(&W3[colg + 1]);
#pragma unroll
        for (int e = 0; e < 4; e++) {
            float dv = acc[nt][e];
            float zv = __shfl_sync(FM, dv, src);
            float gx = __shfl_sync(FM, dv, src + 4);
            float gy = __shfl_sync(FM, dv, src + 8);
            float a  = my_tanh(zv + ((e & 1) ? b1v : b0v));
            float t1 = 1.0f - a * a;
            float t2 = -2.0f * a * t1;
            float L  = fmaf(t2, fmaf(gx, gx, gy * gy), t1 * dv);
            float Lw = L * ((e & 1) ? w1v : w0v);
            if (e < 2) s0 += Lw; else s1 += Lw;
        }
    }
    s0 += __shfl_xor_sync(FM, s0, 1);
    s0 += __shfl_xor_sync(FM, s0, 2);
    s1 += __shfl_xor_sync(FM, s1, 1);
    s1 += __shfl_xor_sync(FM, s1, 2);
    if (c == 3 && q == 0) {
        const int p0 = wm * 4 + (g >> 2);     // row g   -> point p0
        SLAP[p0 * 2 + wn]       = s0;
        SLAP[(p0 + 2) * 2 + wn] = s1;         // row g+8 -> point p0+2
    }
}

// ---------------------------------------------------------------------------
// Interior: HMMA bf16-split Taylor-mode Laplacian. Persistent CTAs,
// 16 warps (warp grid 8m x 2n), register-resident epilogues.
// GEMM rows: r = p*4 + c (p = point 0..31; c = v, gx, gy, L).
// ---------------------------------------------------------------------------
__global__ __launch_bounds__(THREADS_I, 1)
void pinn_interior(const float* __restrict__ xy, const float* __restrict__ f,
                   const float* __restrict__ W0, const float* __restrict__ b0,
                   const float* __restrict__ W1, const float* __restrict__ b1,
                   const float* __restrict__ W2, const float* __restrict__ b2,
                   const float* __restrict__ W3, int n, int ntiles)
{
    extern __shared__ __align__(128) char sm[];
    const u32 smb = smem_to_u32(sm);

    const int tid  = threadIdx.x;
    const int wid  = tid >> 5;
    const int lane = tid & 31;
    const int wm   = wid & 7;
    const int wn   = wid >> 3;

    float* SLAP = (float*)(sm + SM_SLAP);

    // ---- one-time: split + transpose W1/W2 into bf16 hi/lo B^T tiles ----
    for (int idx = tid; idx < H * H; idx += THREADS_I) {
        int k = idx >> 7, nn = idx & 127;     // W[k][nn], coalesced over nn
        u32 off = toff(nn, k);                // B^T cell (row=n, col=k)
        float w1 = W1[idx], w2 = W2[idx];
        __nv_bfloat16 h1 = __float2bfloat16(w1);
        __nv_bfloat16 h2 = __float2bfloat16(w2);
        *(__nv_bfloat16*)(sm + SM_W1HI + off) = h1;
        *(__nv_bfloat16*)(sm + SM_W1LO + off) = __float2bfloat16(w1 - __bfloat162float(h1));
        *(__nv_bfloat16*)(sm + SM_W2HI + off) = h2;
        *(__nv_bfloat16*)(sm + SM_W2LO + off) = __float2bfloat16(w2 - __bfloat162float(h2));
    }
    __syncthreads();

    for (int tile = blockIdx.x; tile < ntiles; tile += gridDim.x) {
        const int base = tile * PTS;

        // ---- layer 0 seed -> A hi/lo tiles ----
        for (int it = tid; it < PTS * 64; it += THREADS_I) {
            int p = it >> 6, j0 = (it & 63) * 2;
            int pt = base + p; if (pt > n - 1) pt = n - 1;
            float x = __ldg(&xy[pt * 2 + 0]);
            float y = __ldg(&xy[pt * 2 + 1]);
            float o[2][4];
#pragma unroll
            for (int jj = 0; jj < 2; jj++) {
                int j = j0 + jj;
                float wx = __ldg(&W0[j]), wy = __ldg(&W0[H + j]);
                float zv = fmaf(x, wx, fmaf(y, wy, __ldg(&b0[j])));
                float a  = my_tanh(zv);
                float t1 = 1.0f - a * a;
                float t2 = -2.0f * a * t1;
                o[jj][0] = a;
                o[jj][1] = t1 * wx;
                o[jj][2] = t1 * wy;
                o[jj][3] = t2 * fmaf(wx, wx, wy * wy);
            }
#pragma unroll
            for (int c = 0; c < 4; c++) {
                u32 off = toff(p * 4 + c, j0);
                float v0 = o[0][c], v1 = o[1][c];
                float h0 = __bfloat162float(__float2bfloat16(v0));
                float h1 = __bfloat162float(__float2bfloat16(v1));
                *(u32*)(sm + SM_AHI + off) = pack2bf(v0, v1);
                *(u32*)(sm + SM_ALO + off) = pack2bf(v0 - h0, v1 - h1);
            }
        }
        __syncthreads();

        float acc[8][4];

        // ---- layer 1 ----
        mainloop(smb, SM_AHI, SM_ALO, SM_W1HI, SM_W1LO, lane, wm, wn, acc);
        __syncthreads();   // all A reads done before epilogue overwrites A
        epi_hidden(sm, b1, lane, wm, wn, acc);
        __syncthreads();   // new A visible

        // ---- layer 2 + output projection ----
        mainloop(smb, SM_AHI, SM_ALO, SM_W2HI, SM_W2LO, lane, wm, wn, acc);
        epi_out(SLAP, b2, W3, lane, wm, wn, acc);
        __syncthreads();

        if (tid == 0) {
            float ssum = 0.0f;
#pragma unroll
            for (int p = 0; p < PTS; p++) {
                int idx = base + p;
                if (idx < n) {
                    float lap = SLAP[p * 2] + SLAP[p * 2 + 1];
                    float d = lap - f[idx];
                    ssum = fmaf(d, d, ssum);
                }
            }
            g_part_int[tile] = ssum;
        }
        __syncthreads();   // SLAP consumed; A safe to overwrite next tile
    }
}

// ---------------------------------------------------------------------------
// Boundary: plain fp32 forward + squared residual (small workload, unchanged).
// ---------------------------------------------------------------------------
__device__ __forceinline__ void hidden1(const float* __restrict__ in,
                                        float* __restrict__ outp,
                                        const float* __restrict__ W,
                                        const float* __restrict__ b,
                                        int j, int p0)
{
    float acc[TB / 2];
#pragma unroll
    for (int p = 0; p < TB / 2; p++) acc[p] = 0.0f;

#pragma unroll 1
    for (int k = 0; k < H; k += 4) {
        const float w0 = W[(k + 0) * H + j];
        const float w1 = W[(k + 1) * H + j];
        const float w2 = W[(k + 2) * H + j];
        const float w3 = W[(k + 3) * H + j];
#pragma unroll
        for (int p = 0; p < TB / 2; p++) {
            const float4 a = *reinterpret_cast<const float4*>(&in[(p0 + p) * H + k]);
            acc[p] = fmaf(a.x, w0, fmaf(a.y, w1, fmaf(a.z, w2, fmaf(a.w, w3, acc[p]))));
        }
    }
    const float bj = b[j];
#pragma unroll
    for (int p = 0; p < TB / 2; p++)
        outp[(p0 + p) * H + j] = my_tanh(acc[p] + bj);
}

__global__ __launch_bounds__(THREADS)
void pinn_boundary(const float* __restrict__ xy, const float* __restrict__ g,
                   const float* __restrict__ W0, const float* __restrict__ b0,
                   const float* __restrict__ W1, const float* __restrict__ b1,
                   const float* __restrict__ W2, const float* __restrict__ b2,
                   const float* __restrict__ W3, const float* __restrict__ b3,
                   int n)
{
    __shared__ __align__(16) float A[TB * H];
    __shared__ __align__(16) float B[TB * H];
    __shared__ float sxy[TB * 2];
    __shared__ float red[TB];

    const int tid  = threadIdx.x;
    const int j    = tid & (H - 1);
    const int p0   = (tid >> 7) * (TB / 2);
    const int base = blockIdx.x * TB;

    if (tid < TB * 2) {
        int pt = base + (tid >> 1);
        if (pt > n - 1) pt = n - 1;
        sxy[tid] = xy[pt * 2 + (tid & 1)];
    }
    __syncthreads();

    {
        const float w0x = W0[j], w0y = W0[H + j], bj = b0[j];
#pragma unroll
        for (int p = 0; p < TB / 2; p++) {
            const int pp = p0 + p;
            A[pp * H + j] = my_tanh(fmaf(sxy[pp * 2], w0x, fmaf(sxy[pp * 2 + 1], w0y, bj)));
        }
    }
    __syncthreads();
    hidden1(A, B, W1, b1, j, p0);
    __syncthreads();
    hidden1(B, A, W2, b2, j, p0);
    __syncthreads();

    if (tid < TB) {
        float v = b3[0];
        for (int k = 0; k < H; k++) v = fmaf(A[tid * H + k], W3[k], v);
        int idx = base + tid;
        if (idx < n) { float d = v - g[idx]; red[tid] = d * d; }
        else red[tid] = 0.0f;
    }
    __syncthreads();

    if (tid == 0) {
        float s = 0.0f;
#pragma unroll
        for (int p = 0; p < TB; p++) s += red[p];
        g_part_bd[blockIdx.x] = s;
    }
}

// ---------------------------------------------------------------------------
__global__ __launch_bounds__(THREADS)
void pinn_finalize(float* __restrict__ out, int nbi, int nbb, int n_int, int n_bd)
{
    __shared__ float s[THREADS];
    const int tid = threadIdx.x;

    float a = 0.0f;
    for (int i = tid; i < nbi; i += THREADS) a += g_part_int[i];
    s[tid] = a;
    __syncthreads();
    for (int st = THREADS / 2; st > 0; st >>= 1) {
        if (tid < st) s[tid] += s[tid + st];
        __syncthreads();
    }
    float loss_f = 0.0f;
    if (tid == 0) loss_f = s[0] * (0.5f / (float)n_int);
    __syncthreads();

    float bsm = 0.0f;
    for (int i = tid; i < nbb; i += THREADS) bsm += g_part_bd[i];
    s[tid] = bsm;
    __syncthreads();
    for (int st = THREADS / 2; st > 0; st >>= 1) {
        if (tid < st) s[tid] += s[tid + st];
        __syncthreads();
    }
    if (tid == 0) {
        out[0] = s[0] * (0.5f / (float)n_bd);
        out[1] = loss_f;
    }
}

// ---------------------------------------------------------------------------
extern "C" void kernel_launch(void* const* d_in, const int* in_sizes, int n_in,
                              void* d_out, int out_size)
{
    const float* xy_int = (const float*)d_in[0];
    const float* f      = (const float*)d_in[1];
    const float* xy_bd  = (const float*)d_in[2];
    const float* g      = (const float*)d_in[3];
    const float* W0     = (const float*)d_in[4];
    const float* b0     = (const float*)d_in[5];
    const float* W1     = (const float*)d_in[6];
    const float* b1     = (const float*)d_in[7];
    const float* W2     = (const float*)d_in[8];
    const float* b2     = (const float*)d_in[9];
    const float* W3     = (const float*)d_in[10];
    const float* b3     = (const float*)d_in[11];

    const int n_int = in_sizes[0] / 2;
    const int n_bd  = in_sizes[2] / 2;

    int ntiles = (n_int + PTS - 1) / PTS;
    if (ntiles > 65536) ntiles = 65536;   // scratch bound (dataset: 8192)
    int gb = (n_bd + TB - 1) / TB;
    if (gb > 8192) gb = 8192;             // scratch bound (dataset: 512)

    int gi = NBLK < ntiles ? NBLK : ntiles;

    cudaFuncSetAttribute(pinn_interior,
                         cudaFuncAttributeMaxDynamicSharedMemorySize, SMEM_TOTAL);

    pinn_interior<<<gi, THREADS_I, SMEM_TOTAL>>>(xy_int, f, W0, b0, W1, b1,
                                                 W2, b2, W3, n_int, ntiles);
    pinn_boundary<<<gb, THREADS>>>(xy_bd, g, W0, b0, W1, b1, W2, b2, W3, b3, n_bd);
    pinn_finalize<<<1, THREADS>>>((float*)d_out, ntiles, gb, n_int, n_bd);
}

// round 13
// speedup vs baseline: 1.2540x; 1.2540x over previous
#include <cuda_runtime.h>
#include <cuda_bf16.h>
#include <math.h>

#define H       128
#define PTS     32      // interior points per tile (M = 4*PTS = 128 rows)
#define TB      32      // boundary points per block
#define THREADS_I 512
#define THREADS 256
#define NBLK    148

typedef unsigned int u32;

// Per-block partial sums (deterministic two-stage reduction; no device mallocs)
__device__ float g_part_int[65536];
__device__ float g_part_bd[8192];

// Accurate tanh independent of -use_fast_math lowering of tanhf.
__device__ __forceinline__ float my_tanh(float x)
{
    float ax = fabsf(x);
    float t  = __expf(-2.0f * ax);
    float r  = (1.0f - t) / (1.0f + t);
    return copysignf(r, x);
}

// ---------------- smem layout (bytes from dynamic base) ----------------
// bf16 tiles: 128 rows x 128 cols, 256 B/row, XOR-swizzled 16B chunks.
#define SM_AHI   0
#define SM_ALO   32768
#define SM_W1HI  65536
#define SM_W1LO  98304
#define SM_W2HI  131072
#define SM_W2LO  163840
#define SM_D     196608                 // fp32 scratch: 128 rows x 68 floats
#define DSTRIDE  68
#define SM_SLAP  (SM_D + 128 * DSTRIDE * 4)   // 231424 (32 floats)
#define SMEM_TOTAL (SM_SLAP + 128)            // 231552 B

// swizzled byte offset inside a bf16 tile: 16B chunk index ^= (row & 7)
__device__ __forceinline__ u32 toff(int row, int col)
{
    return (u32)(row * 256 + ((((col >> 3) ^ (row & 7)) << 4)) + (col & 7) * 2);
}

__device__ __forceinline__ u32 smem_to_u32(const void* p)
{
    u32 a;
    asm("{ .reg .u64 t; cvta.to.shared.u64 t, %1; cvt.u32.u64 %0, t; }"
        : "=r"(a) : "l"(p));
    return a;
}

__device__ __forceinline__ void ldsm4(u32* r, u32 addr)
{
    asm volatile("ldmatrix.sync.aligned.m8n8.x4.shared.b16 {%0,%1,%2,%3}, [%4];"
                 : "=r"(r[0]), "=r"(r[1]), "=r"(r[2]), "=r"(r[3]) : "r"(addr));
}

__device__ __forceinline__ void mma_bf16(float* c, const u32* a, u32 b0, u32 b1)
{
    asm volatile(
        "mma.sync.aligned.m16n8k16.row.col.f32.bf16.bf16.f32 "
        "{%0,%1,%2,%3}, {%4,%5,%6,%7}, {%8,%9}, {%0,%1,%2,%3};"
        : "+f"(c[0]), "+f"(c[1]), "+f"(c[2]), "+f"(c[3])
        : "r"(a[0]), "r"(a[1]), "r"(a[2]), "r"(a[3]), "r"(b0), "r"(b1));
}

__device__ __forceinline__ u32 pack2bf(float a, float b)
{
    return ((u32)__bfloat16_as_ushort(__float2bfloat16(b)) << 16)
         |  (u32)__bfloat16_as_ushort(__float2bfloat16(a));
}

// ---------------------------------------------------------------------------
// 3-term bf16-split GEMM mainloop. Warp (wm, wn): rows 16wm..16wm+15,
// cols 64wn..64wn+63; acc[8][4].  D += Ahi*Bhi + Ahi*Blo + Alo*Bhi.
// ---------------------------------------------------------------------------
__device__ __forceinline__ void mainloop(u32 smb, u32 ahi, u32 alo,
                                         u32 whi, u32 wlo,
                                         int lane, int wm, int wn,
                                         float acc[8][4])
{
#pragma unroll
    for (int i = 0; i < 8; i++)
#pragma unroll
        for (int j = 0; j < 4; j++) acc[i][j] = 0.0f;

    const int arow = wm * 16 + (lane & 15);
    const int ahi4 = lane >> 4;               // 0/1 -> k +8
    const int brl  = ((lane >> 4) & 1) * 8 + (lane & 7);
    const int bko  = (lane >> 3) & 1;         // 0/1 -> k chunk +1

#pragma unroll 2
    for (int s = 0; s < 8; s++) {
        u32 aoffs = (u32)(arow * 256 + (((s * 2 + ahi4) ^ (arow & 7)) << 4));
        u32 ah[4], al[4];
        ldsm4(ah, smb + ahi + aoffs);
        ldsm4(al, smb + alo + aoffs);

        u32 bh[16], bl[16];
#pragma unroll
        for (int jp = 0; jp < 4; jp++) {
            int brow = wn * 64 + jp * 16 + brl;
            u32 boffs = (u32)(brow * 256 + (((s * 2 + bko) ^ (brow & 7)) << 4));
            ldsm4(&bh[jp * 4], smb + whi + boffs);
            ldsm4(&bl[jp * 4], smb + wlo + boffs);
        }

#pragma unroll
        for (int jp = 0; jp < 4; jp++) {      // hi * hi
            mma_bf16(acc[2 * jp],     ah, bh[4 * jp],     bh[4 * jp + 1]);
            mma_bf16(acc[2 * jp + 1], ah, bh[4 * jp + 2], bh[4 * jp + 3]);
        }
#pragma unroll
        for (int jp = 0; jp < 4; jp++) {      // hi * lo
            mma_bf16(acc[2 * jp],     ah, bl[4 * jp],     bl[4 * jp + 1]);
            mma_bf16(acc[2 * jp + 1], ah, bl[4 * jp + 2], bl[4 * jp + 3]);
        }
#pragma unroll
        for (int jp = 0; jp < 4; jp++) {      // lo * hi
            mma_bf16(acc[2 * jp],     al, bh[4 * jp],     bh[4 * jp + 1]);
            mma_bf16(acc[2 * jp + 1], al, bh[4 * jp + 2], bh[4 * jp + 3]);
        }
    }
}

// Store this warp's 64-col D block to fp32 smem scratch (local cols 0..63).
// Called only by warps whose wn matches the half being staged.
__device__ __forceinline__ void store_D(char* sm, const float acc[8][4],
                                        int wm, int lane)
{
    const int g = lane >> 2, q = lane & 3;
    float* D = (float*)(sm + SM_D);
#pragma unroll
    for (int nt = 0; nt < 8; nt++) {
        const int col = nt * 8 + q * 2;
        *(float2*)&D[(wm * 16 + g) * DSTRIDE + col] =
            make_float2(acc[nt][0], acc[nt][1]);
        *(float2*)&D[(wm * 16 + g + 8) * DSTRIDE + col] =
            make_float2(acc[nt][2], acc[nt][3]);
    }
}

// Hidden epilogue for one 64-col half: 512 threads, thread = (point p, 4 cols).
// Reads all 4 channels of its (p, col) quad from D; 1 tanh per (p,col).
__device__ __forceinline__ void epi_hidden_half(char* sm,
                                                const float* __restrict__ b,
                                                int tid, int ch)
{
    const int p = tid >> 4, q = tid & 15;
    const float* D = (const float*)(sm + SM_D);

    float d[4][4];
#pragma unroll
    for (int c = 0; c < 4; c++)
        *(float4*)&d[c][0] = *(const float4*)&D[(4 * p + c) * DSTRIDE + q * 4];

    const int colg = ch * 64 + q * 4;
    float o[4][4];
#pragma unroll
    for (int i = 0; i < 4; i++) {
        float a  = my_tanh(d[0][i] + __ldg(&b[colg + i]));
        float t1 = 1.0f - a * a;
        float t2 = -2.0f * a * t1;
        o[0][i] = a;
        o[1][i] = t1 * d[1][i];
        o[2][i] = t1 * d[2][i];
        o[3][i] = fmaf(t2, fmaf(d[1][i], d[1][i], d[2][i] * d[2][i]),
                       t1 * d[3][i]);
    }

#pragma unroll
    for (int c = 0; c < 4; c++) {
        const int row = 4 * p + c;
        float h0 = __bfloat162float(__float2bfloat16(o[c][0]));
        float h1 = __bfloat162float(__float2bfloat16(o[c][1]));
        float h2 = __bfloat162float(__float2bfloat16(o[c][2]));
        float h3 = __bfloat162float(__float2bfloat16(o[c][3]));
        u32 off0 = toff(row, colg);
        u32 off1 = toff(row, colg + 2);
        *(u32*)(sm + SM_AHI + off0) = pack2bf(o[c][0], o[c][1]);
        *(u32*)(sm + SM_ALO + off0) = pack2bf(o[c][0] - h0, o[c][1] - h1);
        *(u32*)(sm + SM_AHI + off1) = pack2bf(o[c][2], o[c][3]);
        *(u32*)(sm + SM_ALO + off1) = pack2bf(o[c][2] - h2, o[c][3] - h3);
    }
}

// Output epilogue for one half: thread = (point p, 4 cols), returns partial
// lap(p) = sum over its cols of L * W3.
__device__ __forceinline__ float epi_out_half(char* sm,
                                              const float* __restrict__ b2,
                                              const float* __restrict__ W3,
                                              int tid, int ch)
{
    const int p = tid >> 4, q = tid & 15;
    const float* D = (const float*)(sm + SM_D);

    float d[4][4];
#pragma unroll
    for (int c = 0; c < 4; c++)
        *(float4*)&d[c][0] = *(const float4*)&D[(4 * p + c) * DSTRIDE + q * 4];

    const int colg = ch * 64 + q * 4;
    float s = 0.0f;
#pragma unroll
    for (int i = 0; i < 4; i++) {
        float a  = my_tanh(d[0][i] + __ldg(&b2[colg + i]));
        float t1 = 1.0f - a * a;
        float t2 = -2.0f * a * t1;
        float L  = fmaf(t2, fmaf(d[1][i], d[1][i], d[2][i] * d[2][i]),
                        t1 * d[3][i]);
        s = fmaf(L, __ldg(&W3[colg + i]), s);
    }
    return s;
}

// ---------------------------------------------------------------------------
// Interior: HMMA bf16-split Taylor-mode Laplacian. Persistent CTAs,
// 16 warps (warp grid 8m x 2n), smem-D epilogues (no redundant tanh).
// GEMM rows: r = p*4 + c (p = point 0..31; c = v, gx, gy, L).
// ---------------------------------------------------------------------------
__global__ __launch_bounds__(THREADS_I, 1)
void pinn_interior(const float* __restrict__ xy, const float* __restrict__ f,
                   const float* __restrict__ W0, const float* __restrict__ b0,
                   const float* __restrict__ W1, const float* __restrict__ b1,
                   const float* __restrict__ W2, const float* __restrict__ b2,
                   const float* __restrict__ W3, int n, int ntiles)
{
    extern __shared__ __align__(128) char sm[];
    const u32 smb = smem_to_u32(sm);

    const int tid  = threadIdx.x;
    const int wid  = tid >> 5;
    const int lane = tid & 31;
    const int wm   = wid & 7;
    const int wn   = wid >> 3;

    float* SLAP = (float*)(sm + SM_SLAP);

    // ---- one-time: split + transpose W1/W2 into bf16 hi/lo B^T tiles ----
    for (int idx = tid; idx < H * H; idx += THREADS_I) {
        int k = idx >> 7, nn = idx & 127;     // W[k][nn], coalesced over nn
        u32 off = toff(nn, k);                // B^T cell (row=n, col=k)
        float w1 = W1[idx], w2 = W2[idx];
        __nv_bfloat16 h1 = __float2bfloat16(w1);
        __nv_bfloat16 h2 = __float2bfloat16(w2);
        *(__nv_bfloat16*)(sm + SM_W1HI + off) = h1;
        *(__nv_bfloat16*)(sm + SM_W1LO + off) = __float2bfloat16(w1 - __bfloat162float(h1));
        *(__nv_bfloat16*)(sm + SM_W2HI + off) = h2;
        *(__nv_bfloat16*)(sm + SM_W2LO + off) = __float2bfloat16(w2 - __bfloat162float(h2));
    }
    __syncthreads();

    for (int tile = blockIdx.x; tile < ntiles; tile += gridDim.x) {
        const int base = tile * PTS;

        // ---- layer 0 seed -> A hi/lo tiles ----
        for (int it = tid; it < PTS * 64; it += THREADS_I) {
            int p = it >> 6, j0 = (it & 63) * 2;
            int pt = base + p; if (pt > n - 1) pt = n - 1;
            float x = __ldg(&xy[pt * 2 + 0]);
            float y = __ldg(&xy[pt * 2 + 1]);
            float o[2][4];
#pragma unroll
            for (int jj = 0; jj < 2; jj++) {
                int j = j0 + jj;
                float wx = __ldg(&W0[j]), wy = __ldg(&W0[H + j]);
                float zv = fmaf(x, wx, fmaf(y, wy, __ldg(&b0[j])));
                float a  = my_tanh(zv);
                float t1 = 1.0f - a * a;
                float t2 = -2.0f * a * t1;
                o[jj][0] = a;
                o[jj][1] = t1 * wx;
                o[jj][2] = t1 * wy;
                o[jj][3] = t2 * fmaf(wx, wx, wy * wy);
            }
#pragma unroll
            for (int c = 0; c < 4; c++) {
                u32 off = toff(p * 4 + c, j0);
                float v0 = o[0][c], v1 = o[1][c];
                float h0 = __bfloat162float(__float2bfloat16(v0));
                float h1 = __bfloat162float(__float2bfloat16(v1));
                *(u32*)(sm + SM_AHI + off) = pack2bf(v0, v1);
                *(u32*)(sm + SM_ALO + off) = pack2bf(v0 - h0, v1 - h1);
            }
        }
        __syncthreads();

        float acc[8][4];

        // ---- layer 1 ----
        mainloop(smb, SM_AHI, SM_ALO, SM_W1HI, SM_W1LO, lane, wm, wn, acc);
        __syncthreads();                      // A reads done
        if (wn == 0) store_D(sm, acc, wm, lane);
        __syncthreads();
        epi_hidden_half(sm, b1, tid, 0);      // writes A cols 0..63
        __syncthreads();                      // D half-0 consumed
        if (wn == 1) store_D(sm, acc, wm, lane);
        __syncthreads();
        epi_hidden_half(sm, b1, tid, 1);      // writes A cols 64..127
        __syncthreads();                      // new A fully visible

        // ---- layer 2 + output projection ----
        mainloop(smb, SM_AHI, SM_ALO, SM_W2HI, SM_W2LO, lane, wm, wn, acc);
        __syncthreads();
        if (wn == 0) store_D(sm, acc, wm, lane);
        __syncthreads();
        float s = epi_out_half(sm, b2, W3, tid, 0);
        __syncthreads();
        if (wn == 1) store_D(sm, acc, wm, lane);
        __syncthreads();
        s += epi_out_half(sm, b2, W3, tid, 1);

        // reduce over the 16 col-threads of each point (within half-warp)
        s += __shfl_xor_sync(0xffffffffu, s, 1);
        s += __shfl_xor_sync(0xffffffffu, s, 2);
        s += __shfl_xor_sync(0xffffffffu, s, 4);
        s += __shfl_xor_sync(0xffffffffu, s, 8);
        if ((tid & 15) == 0) SLAP[tid >> 4] = s;
        __syncthreads();

        if (tid == 0) {
            float ssum = 0.0f;
#pragma unroll
            for (int p = 0; p < PTS; p++) {
                int idx = base + p;
                if (idx < n) {
                    float d = SLAP[p] - f[idx];
                    ssum = fmaf(d, d, ssum);
                }
            }
            g_part_int[tile] = ssum;
        }
        __syncthreads();                      // SLAP/D consumed before next tile
    }
}

// ---------------------------------------------------------------------------
// Boundary: plain fp32 forward + squared residual (small workload, unchanged).
// ---------------------------------------------------------------------------
__device__ __forceinline__ void hidden1(const float* __restrict__ in,
                                        float* __restrict__ outp,
                                        const float* __restrict__ W,
                                        const float* __restrict__ b,
                                        int j, int p0)
{
    float acc[TB / 2];
#pragma unroll
    for (int p = 0; p < TB / 2; p++) acc[p] = 0.0f;

#pragma unroll 1
    for (int k = 0; k < H; k += 4) {
        const float w0 = W[(k + 0) * H + j];
        const float w1 = W[(k + 1) * H + j];
        const float w2 = W[(k + 2) * H + j];
        const float w3 = W[(k + 3) * H + j];
#pragma unroll
        for (int p = 0; p < TB / 2; p++) {
            const float4 a = *reinterpret_cast<const float4*>(&in[(p0 + p) * H + k]);
            acc[p] = fmaf(a.x, w0, fmaf(a.y, w1, fmaf(a.z, w2, fmaf(a.w, w3, acc[p]))));
        }
    }
    const float bj = b[j];
#pragma unroll
    for (int p = 0; p < TB / 2; p++)
        outp[(p0 + p) * H + j] = my_tanh(acc[p] + bj);
}

__global__ __launch_bounds__(THREADS)
void pinn_boundary(const float* __restrict__ xy, const float* __restrict__ g,
                   const float* __restrict__ W0, const float* __restrict__ b0,
                   const float* __restrict__ W1, const float* __restrict__ b1,
                   const float* __restrict__ W2, const float* __restrict__ b2,
                   const float* __restrict__ W3, const float* __restrict__ b3,
                   int n)
{
    __shared__ __align__(16) float A[TB * H];
    __shared__ __align__(16) float B[TB * H];
    __shared__ float sxy[TB * 2];
    __shared__ float red[TB];

    const int tid  = threadIdx.x;
    const int j    = tid & (H - 1);
    const int p0   = (tid >> 7) * (TB / 2);
    const int base = blockIdx.x * TB;

    if (tid < TB * 2) {
        int pt = base + (tid >> 1);
        if (pt > n - 1) pt = n - 1;
        sxy[tid] = xy[pt * 2 + (tid & 1)];
    }
    __syncthreads();

    {
        const float w0x = W0[j], w0y = W0[H + j], bj = b0[j];
#pragma unroll
        for (int p = 0; p < TB / 2; p++) {
            const int pp = p0 + p;
            A[pp * H + j] = my_tanh(fmaf(sxy[pp * 2], w0x, fmaf(sxy[pp * 2 + 1], w0y, bj)));
        }
    }
    __syncthreads();
    hidden1(A, B, W1, b1, j, p0);
    __syncthreads();
    hidden1(B, A, W2, b2, j, p0);
    __syncthreads();

    if (tid < TB) {
        float v = b3[0];
        for (int k = 0; k < H; k++) v = fmaf(A[tid * H + k], W3[k], v);
        int idx = base + tid;
        if (idx < n) { float d = v - g[idx]; red[tid] = d * d; }
        else red[tid] = 0.0f;
    }
    __syncthreads();

    if (tid == 0) {
        float s = 0.0f;
#pragma unroll
        for (int p = 0; p < TB; p++) s += red[p];
        g_part_bd[blockIdx.x] = s;
    }
}

// ---------------------------------------------------------------------------
__global__ __launch_bounds__(THREADS)
void pinn_finalize(float* __restrict__ out, int nbi, int nbb, int n_int, int n_bd)
{
    __shared__ float s[THREADS];
    const int tid = threadIdx.x;

    float a = 0.0f;
    for (int i = tid; i < nbi; i += THREADS) a += g_part_int[i];
    s[tid] = a;
    __syncthreads();
    for (int st = THREADS / 2; st > 0; st >>= 1) {
        if (tid < st) s[tid] += s[tid + st];
        __syncthreads();
    }
    float loss_f = 0.0f;
    if (tid == 0) loss_f = s[0] * (0.5f / (float)n_int);
    __syncthreads();

    float bsm = 0.0f;
    for (int i = tid; i < nbb; i += THREADS) bsm += g_part_bd[i];
    s[tid] = bsm;
    __syncthreads();
    for (int st = THREADS / 2; st > 0; st >>= 1) {
        if (tid < st) s[tid] += s[tid + st];
        __syncthreads();
    }
    if (tid == 0) {
        out[0] = s[0] * (0.5f / (float)n_bd);
        out[1] = loss_f;
    }
}

// ---------------------------------------------------------------------------
extern "C" void kernel_launch(void* const* d_in, const int* in_sizes, int n_in,
                              void* d_out, int out_size)
{
    const float* xy_int = (const float*)d_in[0];
    const float* f      = (const float*)d_in[1];
    const float* xy_bd  = (const float*)d_in[2];
    const float* g      = (const float*)d_in[3];
    const float* W0     = (const float*)d_in[4];
    const float* b0     = (const float*)d_in[5];
    const float* W1     = (const float*)d_in[6];
    const float* b1     = (const float*)d_in[7];
    const float* W2     = (const float*)d_in[8];
    const float* b2     = (const float*)d_in[9];
    const float* W3     = (const float*)d_in[10];
    const float* b3     = (const float*)d_in[11];

    const int n_int = in_sizes[0] / 2;
    const int n_bd  = in_sizes[2] / 2;

    int ntiles = (n_int + PTS - 1) / PTS;
    if (ntiles > 65536) ntiles = 65536;   // scratch bound (dataset: 8192)
    int gb = (n_bd + TB - 1) / TB;
    if (gb > 8192) gb = 8192;             // scratch bound (dataset: 512)

    int gi = NBLK < ntiles ? NBLK : ntiles;

    cudaFuncSetAttribute(pinn_interior,
                         cudaFuncAttributeMaxDynamicSharedMemorySize, SMEM_TOTAL);

    pinn_interior<<<gi, THREADS_I, SMEM_TOTAL>>>(xy_int, f, W0, b0, W1, b1,
                                                 W2, b2, W3, n_int, ntiles);
    pinn_boundary<<<gb, THREADS>>>(xy_bd, g, W0, b0, W1, b1, W2, b2, W3, b3, n_bd);
    pinn_finalize<<<1, THREADS>>>((float*)d_out, ntiles, gb, n_int, n_bd);
}

// round 14
// speedup vs baseline: 1.3690x; 1.0917x over previous
#include <cuda_runtime.h>
#include <cuda_bf16.h>
#include <math.h>

#define H       128
#define PTS     32      // interior points per tile (M = 4*PTS = 128 rows)
#define TB      32      // boundary points per block
#define THREADS_I 512
#define THREADS 256
#define NBLK    148

typedef unsigned int u32;

// Per-block partial sums (deterministic two-stage reduction; no device mallocs)
__device__ float g_part_int[65536];
__device__ float g_part_bd[8192];

// tanh with a GUARANTEED fast path (explicit MUFU ex2/rcp), independent of
// -use_fast_math: 2 MUFU + ~5 ALU. rel err ~2^-21, fine vs 1e-3 budget.
__device__ __forceinline__ float my_tanh(float x)
{
    const float NL2E2 = -2.8853900817779268f;   // -2*log2(e)
    float ax = fabsf(x);
    float e;
    asm("ex2.approx.f32 %0, %1;" : "=f"(e) : "f"(ax * NL2E2)); // exp(-2|x|)
    float r;
    float den = 1.0f + e;
    asm("rcp.approx.f32 %0, %1;" : "=f"(r) : "f"(den));
    return copysignf((1.0f - e) * r, x);
}

// ---------------- smem layout (bytes from dynamic base) ----------------
// bf16 tiles: 128 rows x 128 cols, 256 B/row, XOR-swizzled 16B chunks.
#define SM_AHI   0
#define SM_ALO   32768
#define SM_W1HI  65536
#define SM_W1LO  98304
#define SM_W2HI  131072
#define SM_W2LO  163840
#define SM_D     196608                 // fp32 scratch: 128 rows x 68 floats
#define DSTRIDE  68
#define SM_SLAP  (SM_D + 128 * DSTRIDE * 4)   // 231424 (32 floats)
#define SMEM_TOTAL (SM_SLAP + 128)            // 231552 B

// swizzled byte offset inside a bf16 tile: 16B chunk index ^= (row & 7)
__device__ __forceinline__ u32 toff(int row, int col)
{
    return (u32)(row * 256 + ((((col >> 3) ^ (row & 7)) << 4)) + (col & 7) * 2);
}

__device__ __forceinline__ u32 smem_to_u32(const void* p)
{
    u32 a;
    asm("{ .reg .u64 t; cvta.to.shared.u64 t, %1; cvt.u32.u64 %0, t; }"
        : "=r"(a) : "l"(p));
    return a;
}

__device__ __forceinline__ void ldsm4(u32* r, u32 addr)
{
    asm volatile("ldmatrix.sync.aligned.m8n8.x4.shared.b16 {%0,%1,%2,%3}, [%4];"
                 : "=r"(r[0]), "=r"(r[1]), "=r"(r[2]), "=r"(r[3]) : "r"(addr));
}

__device__ __forceinline__ void mma_bf16(float* c, const u32* a, u32 b0, u32 b1)
{
    asm volatile(
        "mma.sync.aligned.m16n8k16.row.col.f32.bf16.bf16.f32 "
        "{%0,%1,%2,%3}, {%4,%5,%6,%7}, {%8,%9}, {%0,%1,%2,%3};"
        : "+f"(c[0]), "+f"(c[1]), "+f"(c[2]), "+f"(c[3])
        : "r"(a[0]), "r"(a[1]), "r"(a[2]), "r"(a[3]), "r"(b0), "r"(b1));
}

__device__ __forceinline__ u32 pack2bf(float a, float b)
{
    return ((u32)__bfloat16_as_ushort(__float2bfloat16(b)) << 16)
         |  (u32)__bfloat16_as_ushort(__float2bfloat16(a));
}

// ---------------------------------------------------------------------------
// 3-term bf16-split GEMM mainloop. Warp (wm, wn): rows 16wm..16wm+15,
// cols 64wn..64wn+63; acc[8][4].  D += Ahi*Bhi + Ahi*Blo + Alo*Bhi.
// ---------------------------------------------------------------------------
__device__ __forceinline__ void mainloop(u32 smb, u32 ahi, u32 alo,
                                         u32 whi, u32 wlo,
                                         int lane, int wm, int wn,
                                         float acc[8][4])
{
#pragma unroll
    for (int i = 0; i < 8; i++)
#pragma unroll
        for (int j = 0; j < 4; j++) acc[i][j] = 0.0f;

    const int arow = wm * 16 + (lane & 15);
    const int ahi4 = lane >> 4;               // 0/1 -> k +8
    const int brl  = ((lane >> 4) & 1) * 8 + (lane & 7);
    const int bko  = (lane >> 3) & 1;         // 0/1 -> k chunk +1

#pragma unroll 2
    for (int s = 0; s < 8; s++) {
        u32 aoffs = (u32)(arow * 256 + (((s * 2 + ahi4) ^ (arow & 7)) << 4));
        u32 ah[4], al[4];
        ldsm4(ah, smb + ahi + aoffs);
        ldsm4(al, smb + alo + aoffs);

        u32 bh[16], bl[16];
#pragma unroll
        for (int jp = 0; jp < 4; jp++) {
            int brow = wn * 64 + jp * 16 + brl;
            u32 boffs = (u32)(brow * 256 + (((s * 2 + bko) ^ (brow & 7)) << 4));
            ldsm4(&bh[jp * 4], smb + whi + boffs);
            ldsm4(&bl[jp * 4], smb + wlo + boffs);
        }

#pragma unroll
        for (int jp = 0; jp < 4; jp++) {      // hi * hi
            mma_bf16(acc[2 * jp],     ah, bh[4 * jp],     bh[4 * jp + 1]);
            mma_bf16(acc[2 * jp + 1], ah, bh[4 * jp + 2], bh[4 * jp + 3]);
        }
#pragma unroll
        for (int jp = 0; jp < 4; jp++) {      // hi * lo
            mma_bf16(acc[2 * jp],     ah, bl[4 * jp],     bl[4 * jp + 1]);
            mma_bf16(acc[2 * jp + 1], ah, bl[4 * jp + 2], bl[4 * jp + 3]);
        }
#pragma unroll
        for (int jp = 0; jp < 4; jp++) {      // lo * hi
            mma_bf16(acc[2 * jp],     al, bh[4 * jp],     bh[4 * jp + 1]);
            mma_bf16(acc[2 * jp + 1], al, bh[4 * jp + 2], bh[4 * jp + 3]);
        }
    }
}

// Store this warp's 64-col D block to fp32 smem scratch (local cols 0..63).
__device__ __forceinline__ void store_D(char* sm, const float acc[8][4],
                                        int wm, int lane)
{
    const int g = lane >> 2, q = lane & 3;
    float* D = (float*)(sm + SM_D);
#pragma unroll
    for (int nt = 0; nt < 8; nt++) {
        const int col = nt * 8 + q * 2;
        *(float2*)&D[(wm * 16 + g) * DSTRIDE + col] =
            make_float2(acc[nt][0], acc[nt][1]);
        *(float2*)&D[(wm * 16 + g + 8) * DSTRIDE + col] =
            make_float2(acc[nt][2], acc[nt][3]);
    }
}

// Hidden epilogue for one 64-col half: 512 threads, thread = (point p, 4 cols).
// Reads all 4 channels of its (p, col) quad from D; 1 tanh per (p,col).
// A-tile writes packed as uint2 (cols 4q..4q+3 lie within one 16B chunk).
__device__ __forceinline__ void epi_hidden_half(char* sm,
                                                const float* __restrict__ b,
                                                int tid, int ch)
{
    const int p = tid >> 4, q = tid & 15;
    const float* D = (const float*)(sm + SM_D);

    float d[4][4];
#pragma unroll
    for (int c = 0; c < 4; c++)
        *(float4*)&d[c][0] = *(const float4*)&D[(4 * p + c) * DSTRIDE + q * 4];

    const int colg = ch * 64 + q * 4;
    float o[4][4];
#pragma unroll
    for (int i = 0; i < 4; i++) {
        float a  = my_tanh(d[0][i] + __ldg(&b[colg + i]));
        float t1 = 1.0f - a * a;
        float t2 = -2.0f * a * t1;
        o[0][i] = a;
        o[1][i] = t1 * d[1][i];
        o[2][i] = t1 * d[2][i];
        o[3][i] = fmaf(t2, fmaf(d[1][i], d[1][i], d[2][i] * d[2][i]),
                       t1 * d[3][i]);
    }

#pragma unroll
    for (int c = 0; c < 4; c++) {
        const int row = 4 * p + c;
        float h0 = __bfloat162float(__float2bfloat16(o[c][0]));
        float h1 = __bfloat162float(__float2bfloat16(o[c][1]));
        float h2 = __bfloat162float(__float2bfloat16(o[c][2]));
        float h3 = __bfloat162float(__float2bfloat16(o[c][3]));
        u32 off0 = toff(row, colg);           // 8-byte aligned (colg%8 in {0,4})
        *(uint2*)(sm + SM_AHI + off0) =
            make_uint2(pack2bf(o[c][0], o[c][1]), pack2bf(o[c][2], o[c][3]));
        *(uint2*)(sm + SM_ALO + off0) =
            make_uint2(pack2bf(o[c][0] - h0, o[c][1] - h1),
                       pack2bf(o[c][2] - h2, o[c][3] - h3));
    }
}

// Output epilogue for one half: thread = (point p, 4 cols), partial lap.
__device__ __forceinline__ float epi_out_half(char* sm,
                                              const float* __restrict__ b2,
                                              const float* __restrict__ W3,
                                              int tid, int ch)
{
    const int p = tid >> 4, q = tid & 15;
    const float* D = (const float*)(sm + SM_D);

    float d[4][4];
#pragma unroll
    for (int c = 0; c < 4; c++)
        *(float4*)&d[c][0] = *(const float4*)&D[(4 * p + c) * DSTRIDE + q * 4];

    const int colg = ch * 64 + q * 4;
    float s = 0.0f;
#pragma unroll
    for (int i = 0; i < 4; i++) {
        float a  = my_tanh(d[0][i] + __ldg(&b2[colg + i]));
        float t1 = 1.0f - a * a;
        float t2 = -2.0f * a * t1;
        float L  = fmaf(t2, fmaf(d[1][i], d[1][i], d[2][i] * d[2][i]),
                        t1 * d[3][i]);
        s = fmaf(L, __ldg(&W3[colg + i]), s);
    }
    return s;
}

// ---------------------------------------------------------------------------
// Interior: HMMA bf16-split Taylor-mode Laplacian. Persistent CTAs,
// 16 warps (warp grid 8m x 2n), smem-D epilogues (no redundant tanh).
// GEMM rows: r = p*4 + c (p = point 0..31; c = v, gx, gy, L).
// ---------------------------------------------------------------------------
__global__ __launch_bounds__(THREADS_I, 1)
void pinn_interior(const float* __restrict__ xy, const float* __restrict__ f,
                   const float* __restrict__ W0, const float* __restrict__ b0,
                   const float* __restrict__ W1, const float* __restrict__ b1,
                   const float* __restrict__ W2, const float* __restrict__ b2,
                   const float* __restrict__ W3, int n, int ntiles)
{
    extern __shared__ __align__(128) char sm[];
    const u32 smb = smem_to_u32(sm);

    const int tid  = threadIdx.x;
    const int wid  = tid >> 5;
    const int lane = tid & 31;
    const int wm   = wid & 7;
    const int wn   = wid >> 3;

    float* SLAP = (float*)(sm + SM_SLAP);

    // ---- one-time: split + transpose W1/W2 into bf16 hi/lo B^T tiles ----
    for (int idx = tid; idx < H * H; idx += THREADS_I) {
        int k = idx >> 7, nn = idx & 127;     // W[k][nn], coalesced over nn
        u32 off = toff(nn, k);                // B^T cell (row=n, col=k)
        float w1 = W1[idx], w2 = W2[idx];
        __nv_bfloat16 h1 = __float2bfloat16(w1);
        __nv_bfloat16 h2 = __float2bfloat16(w2);
        *(__nv_bfloat16*)(sm + SM_W1HI + off) = h1;
        *(__nv_bfloat16*)(sm + SM_W1LO + off) = __float2bfloat16(w1 - __bfloat162float(h1));
        *(__nv_bfloat16*)(sm + SM_W2HI + off) = h2;
        *(__nv_bfloat16*)(sm + SM_W2LO + off) = __float2bfloat16(w2 - __bfloat162float(h2));
    }
    __syncthreads();

    for (int tile = blockIdx.x; tile < ntiles; tile += gridDim.x) {
        const int base = tile * PTS;

        // ---- layer 0 seed -> A hi/lo tiles (thread = point x 4 units) ----
        for (int it = tid; it < PTS * 32; it += THREADS_I) {
            int p = it >> 5, j0 = (it & 31) * 4;
            int pt = base + p; if (pt > n - 1) pt = n - 1;
            float x = __ldg(&xy[pt * 2 + 0]);
            float y = __ldg(&xy[pt * 2 + 1]);
            float o[4][4];   // [unit][channel]
#pragma unroll
            for (int jj = 0; jj < 4; jj++) {
                int j = j0 + jj;
                float wx = __ldg(&W0[j]), wy = __ldg(&W0[H + j]);
                float zv = fmaf(x, wx, fmaf(y, wy, __ldg(&b0[j])));
                float a  = my_tanh(zv);
                float t1 = 1.0f - a * a;
                float t2 = -2.0f * a * t1;
                o[jj][0] = a;
                o[jj][1] = t1 * wx;
                o[jj][2] = t1 * wy;
                o[jj][3] = t2 * fmaf(wx, wx, wy * wy);
            }
#pragma unroll
            for (int c = 0; c < 4; c++) {
                u32 off = toff(p * 4 + c, j0);   // 8B-aligned (j0 % 8 in {0,4})
                float v0 = o[0][c], v1 = o[1][c], v2 = o[2][c], v3 = o[3][c];
                float h0 = __bfloat162float(__float2bfloat16(v0));
                float h1 = __bfloat162float(__float2bfloat16(v1));
                float h2 = __bfloat162float(__float2bfloat16(v2));
                float h3 = __bfloat162float(__float2bfloat16(v3));
                *(uint2*)(sm + SM_AHI + off) =
                    make_uint2(pack2bf(v0, v1), pack2bf(v2, v3));
                *(uint2*)(sm + SM_ALO + off) =
                    make_uint2(pack2bf(v0 - h0, v1 - h1),
                               pack2bf(v2 - h2, v3 - h3));
            }
        }
        __syncthreads();

        float acc[8][4];

        // ---- layer 1 ----
        mainloop(smb, SM_AHI, SM_ALO, SM_W1HI, SM_W1LO, lane, wm, wn, acc);
        __syncthreads();                      // A reads done
        if (wn == 0) store_D(sm, acc, wm, lane);
        __syncthreads();
        epi_hidden_half(sm, b1, tid, 0);      // writes A cols 0..63
        __syncthreads();                      // D half-0 consumed
        if (wn == 1) store_D(sm, acc, wm, lane);
        __syncthreads();
        epi_hidden_half(sm, b1, tid, 1);      // writes A cols 64..127
        __syncthreads();                      // new A fully visible

        // ---- layer 2 + output projection ----
        mainloop(smb, SM_AHI, SM_ALO, SM_W2HI, SM_W2LO, lane, wm, wn, acc);
        __syncthreads();
        if (wn == 0) store_D(sm, acc, wm, lane);
        __syncthreads();
        float s = epi_out_half(sm, b2, W3, tid, 0);
        __syncthreads();
        if (wn == 1) store_D(sm, acc, wm, lane);
        __syncthreads();
        s += epi_out_half(sm, b2, W3, tid, 1);

        // reduce over the 16 col-threads of each point (within half-warp)
        s += __shfl_xor_sync(0xffffffffu, s, 1);
        s += __shfl_xor_sync(0xffffffffu, s, 2);
        s += __shfl_xor_sync(0xffffffffu, s, 4);
        s += __shfl_xor_sync(0xffffffffu, s, 8);
        if ((tid & 15) == 0) SLAP[tid >> 4] = s;
        __syncthreads();

        // warp 0: parallel squared-residual reduction (deterministic)
        if (wid == 0) {
            int idx = base + lane;
            float d = 0.0f;
            if (idx < n) d = SLAP[lane] - f[idx];
            float v = d * d;
            v += __shfl_xor_sync(0xffffffffu, v, 1);
            v += __shfl_xor_sync(0xffffffffu, v, 2);
            v += __shfl_xor_sync(0xffffffffu, v, 4);
            v += __shfl_xor_sync(0xffffffffu, v, 8);
            v += __shfl_xor_sync(0xffffffffu, v, 16);
            if (lane == 0) g_part_int[tile] = v;
        }
        __syncthreads();                      // SLAP/D consumed before next tile
    }
}

// ---------------------------------------------------------------------------
// Boundary: plain fp32 forward + squared residual (small workload, unchanged).
// ---------------------------------------------------------------------------
__device__ __forceinline__ void hidden1(const float* __restrict__ in,
                                        float* __restrict__ outp,
                                        const float* __restrict__ W,
                                        const float* __restrict__ b,
                                        int j, int p0)
{
    float acc[TB / 2];
#pragma unroll
    for (int p = 0; p < TB / 2; p++) acc[p] = 0.0f;

#pragma unroll 1
    for (int k = 0; k < H; k += 4) {
        const float w0 = W[(k + 0) * H + j];
        const float w1 = W[(k + 1) * H + j];
        const float w2 = W[(k + 2) * H + j];
        const float w3 = W[(k + 3) * H + j];
#pragma unroll
        for (int p = 0; p < TB / 2; p++) {
            const float4 a = *reinterpret_cast<const float4*>(&in[(p0 + p) * H + k]);
            acc[p] = fmaf(a.x, w0, fmaf(a.y, w1, fmaf(a.z, w2, fmaf(a.w, w3, acc[p]))));
        }
    }
    const float bj = b[j];
#pragma unroll
    for (int p = 0; p < TB / 2; p++)
        outp[(p0 + p) * H + j] = my_tanh(acc[p] + bj);
}

__global__ __launch_bounds__(THREADS)
void pinn_boundary(const float* __restrict__ xy, const float* __restrict__ g,
                   const float* __restrict__ W0, const float* __restrict__ b0,
                   const float* __restrict__ W1, const float* __restrict__ b1,
                   const float* __restrict__ W2, const float* __restrict__ b2,
                   const float* __restrict__ W3, const float* __restrict__ b3,
                   int n)
{
    __shared__ __align__(16) float A[TB * H];
    __shared__ __align__(16) float B[TB * H];
    __shared__ float sxy[TB * 2];
    __shared__ float red[TB];

    const int tid  = threadIdx.x;
    const int j    = tid & (H - 1);
    const int p0   = (tid >> 7) * (TB / 2);
    const int base = blockIdx.x * TB;

    if (tid < TB * 2) {
        int pt = base + (tid >> 1);
        if (pt > n - 1) pt = n - 1;
        sxy[tid] = xy[pt * 2 + (tid & 1)];
    }
    __syncthreads();

    {
        const float w0x = W0[j], w0y = W0[H + j], bj = b0[j];
#pragma unroll
        for (int p = 0; p < TB / 2; p++) {
            const int pp = p0 + p;
            A[pp * H + j] = my_tanh(fmaf(sxy[pp * 2], w0x, fmaf(sxy[pp * 2 + 1], w0y, bj)));
        }
    }
    __syncthreads();
    hidden1(A, B, W1, b1, j, p0);
    __syncthreads();
    hidden1(B, A, W2, b2, j, p0);
    __syncthreads();

    if (tid < TB) {
        float v = b3[0];
        for (int k = 0; k < H; k++) v = fmaf(A[tid * H + k], W3[k], v);
        int idx = base + tid;
        if (idx < n) { float d = v - g[idx]; red[tid] = d * d; }
        else red[tid] = 0.0f;
    }
    __syncthreads();

    if (tid == 0) {
        float s = 0.0f;
#pragma unroll
        for (int p = 0; p < TB; p++) s += red[p];
        g_part_bd[blockIdx.x] = s;
    }
}

// ---------------------------------------------------------------------------
__global__ __launch_bounds__(THREADS)
void pinn_finalize(float* __restrict__ out, int nbi, int nbb, int n_int, int n_bd)
{
    __shared__ float s[THREADS];
    const int tid = threadIdx.x;

    float a = 0.0f;
    for (int i = tid; i < nbi; i += THREADS) a += g_part_int[i];
    s[tid] = a;
    __syncthreads();
    for (int st = THREADS / 2; st > 0; st >>= 1) {
        if (tid < st) s[tid] += s[tid + st];
        __syncthreads();
    }
    float loss_f = 0.0f;
    if (tid == 0) loss_f = s[0] * (0.5f / (float)n_int);
    __syncthreads();

    float bsm = 0.0f;
    for (int i = tid; i < nbb; i += THREADS) bsm += g_part_bd[i];
    s[tid] = bsm;
    __syncthreads();
    for (int st = THREADS / 2; st > 0; st >>= 1) {
        if (tid < st) s[tid] += s[tid + st];
        __syncthreads();
    }
    if (tid == 0) {
        out[0] = s[0] * (0.5f / (float)n_bd);
        out[1] = loss_f;
    }
}

// ---------------------------------------------------------------------------
extern "C" void kernel_launch(void* const* d_in, const int* in_sizes, int n_in,
                              void* d_out, int out_size)
{
    const float* xy_int = (const float*)d_in[0];
    const float* f      = (const float*)d_in[1];
    const float* xy_bd  = (const float*)d_in[2];
    const float* g      = (const float*)d_in[3];
    const float* W0     = (const float*)d_in[4];
    const float* b0     = (const float*)d_in[5];
    const float* W1     = (const float*)d_in[6];
    const float* b1     = (const float*)d_in[7];
    const float* W2     = (const float*)d_in[8];
    const float* b2     = (const float*)d_in[9];
    const float* W3     = (const float*)d_in[10];
    const float* b3     = (const float*)d_in[11];

    const int n_int = in_sizes[0] / 2;
    const int n_bd  = in_sizes[2] / 2;

    int ntiles = (n_int + PTS - 1) / PTS;
    if (ntiles > 65536) ntiles = 65536;   // scratch bound (dataset: 8192)
    int gb = (n_bd + TB - 1) / TB;
    if (gb > 8192) gb = 8192;             // scratch bound (dataset: 512)

    int gi = NBLK < ntiles ? NBLK : ntiles;

    cudaFuncSetAttribute(pinn_interior,
                         cudaFuncAttributeMaxDynamicSharedMemorySize, SMEM_TOTAL);

    pinn_interior<<<gi, THREADS_I, SMEM_TOTAL>>>(xy_int, f, W0, b0, W1, b1,
                                                 W2, b2, W3, n_int, ntiles);
    pinn_boundary<<<gb, THREADS>>>(xy_bd, g, W0, b0, W1, b1, W2, b2, W3, b3, n_bd);
    pinn_finalize<<<1, THREADS>>>((float*)d_out, ntiles, gb, n_int, n_bd);
}

// round 15
// speedup vs baseline: 1.6871x; 1.2323x over previous
#include <cuda_runtime.h>
#include <cuda_bf16.h>
#include <math.h>

#define H       128
#define PTS     32      // interior points per tile (M = 4*PTS = 128 rows)
#define TB      32      // boundary points per block
#define THREADS_I 512
#define THREADS 256
#define NBLK    148

typedef unsigned int u32;

// Per-pair partial sums (tile*8 + pair); deterministic two-stage reduction.
__device__ float g_part_int[65536];
__device__ float g_part_bd[8192];

// tanh with a GUARANTEED fast path (explicit MUFU ex2/rcp), independent of
// -use_fast_math: 2 MUFU + ~5 ALU. rel err ~2^-21, fine vs 1e-3 budget.
__device__ __forceinline__ float my_tanh(float x)
{
    const float NL2E2 = -2.8853900817779268f;   // -2*log2(e)
    float ax = fabsf(x);
    float e;
    asm("ex2.approx.f32 %0, %1;" : "=f"(e) : "f"(ax * NL2E2)); // exp(-2|x|)
    float r;
    float den = 1.0f + e;
    asm("rcp.approx.f32 %0, %1;" : "=f"(r) : "f"(den));
    return copysignf((1.0f - e) * r, x);
}

// ---------------- smem layout (bytes from dynamic base) ----------------
// bf16 tiles: 128 rows x 128 cols, 256 B/row, XOR-swizzled 16B chunks.
#define SM_AHI   0
#define SM_ALO   32768
#define SM_W1HI  65536
#define SM_W1LO  98304
#define SM_W2HI  131072
#define SM_W2LO  163840
#define SM_TS    196608                 // per-warp transpose scratch
#define TS_WARP  1280                   // 16 x 18 fp32 = 1152, padded
#define SM_SLAP  (SM_TS + 16 * TS_WARP) // 217088 : 64 floats
#define SMEM_TOTAL (SM_SLAP + 256)      // 217344 B

// swizzled byte offset inside a bf16 tile: 16B chunk index ^= (row & 7)
__device__ __forceinline__ u32 toff(int row, int col)
{
    return (u32)(row * 256 + ((((col >> 3) ^ (row & 7)) << 4)) + (col & 7) * 2);
}

__device__ __forceinline__ u32 smem_to_u32(const void* p)
{
    u32 a;
    asm("{ .reg .u64 t; cvta.to.shared.u64 t, %1; cvt.u32.u64 %0, t; }"
        : "=r"(a) : "l"(p));
    return a;
}

__device__ __forceinline__ void ldsm4(u32* r, u32 addr)
{
    asm volatile("ldmatrix.sync.aligned.m8n8.x4.shared.b16 {%0,%1,%2,%3}, [%4];"
                 : "=r"(r[0]), "=r"(r[1]), "=r"(r[2]), "=r"(r[3]) : "r"(addr));
}

__device__ __forceinline__ void mma_bf16(float* c, const u32* a, u32 b0, u32 b1)
{
    asm volatile(
        "mma.sync.aligned.m16n8k16.row.col.f32.bf16.bf16.f32 "
        "{%0,%1,%2,%3}, {%4,%5,%6,%7}, {%8,%9}, {%0,%1,%2,%3};"
        : "+f"(c[0]), "+f"(c[1]), "+f"(c[2]), "+f"(c[3])
        : "r"(a[0]), "r"(a[1]), "r"(a[2]), "r"(a[3]), "r"(b0), "r"(b1));
}

__device__ __forceinline__ u32 pack2bf(float a, float b)
{
    return ((u32)__bfloat16_as_ushort(__float2bfloat16(b)) << 16)
         |  (u32)__bfloat16_as_ushort(__float2bfloat16(a));
}

// pair-scoped named barrier (64 threads: warps wm and 8+wm), ids 1..8
#define PBAR(id) asm volatile("bar.sync %0, %1;" :: "r"((id)), "r"(64) : "memory")

// ---------------------------------------------------------------------------
// 3-term bf16-split GEMM mainloop. Warp (wm, wn): rows 16wm..16wm+15,
// cols 64wn..64wn+63; acc[8][4].  D += Ahi*Bhi + Ahi*Blo + Alo*Bhi.
// Reads ONLY its own 16 A rows (pair-private) + static weight tiles.
// ---------------------------------------------------------------------------
__device__ __forceinline__ void mainloop(u32 smb, u32 ahi, u32 alo,
                                         u32 whi, u32 wlo,
                                         int lane, int wm, int wn,
                                         float acc[8][4])
{
#pragma unroll
    for (int i = 0; i < 8; i++)
#pragma unroll
        for (int j = 0; j < 4; j++) acc[i][j] = 0.0f;

    const int arow = wm * 16 + (lane & 15);
    const int ahi4 = lane >> 4;               // 0/1 -> k +8
    const int brl  = ((lane >> 4) & 1) * 8 + (lane & 7);
    const int bko  = (lane >> 3) & 1;         // 0/1 -> k chunk +1

#pragma unroll 2
    for (int s = 0; s < 8; s++) {
        u32 aoffs = (u32)(arow * 256 + (((s * 2 + ahi4) ^ (arow & 7)) << 4));
        u32 ah[4], al[4];
        ldsm4(ah, smb + ahi + aoffs);
        ldsm4(al, smb + alo + aoffs);

        u32 bh[16], bl[16];
#pragma unroll
        for (int jp = 0; jp < 4; jp++) {
            int brow = wn * 64 + jp * 16 + brl;
            u32 boffs = (u32)(brow * 256 + (((s * 2 + bko) ^ (brow & 7)) << 4));
            ldsm4(&bh[jp * 4], smb + whi + boffs);
            ldsm4(&bl[jp * 4], smb + wlo + boffs);
        }

#pragma unroll
        for (int jp = 0; jp < 4; jp++) {      // hi * hi
            mma_bf16(acc[2 * jp],     ah, bh[4 * jp],     bh[4 * jp + 1]);
            mma_bf16(acc[2 * jp + 1], ah, bh[4 * jp + 2], bh[4 * jp + 3]);
        }
#pragma unroll
        for (int jp = 0; jp < 4; jp++) {      // hi * lo
            mma_bf16(acc[2 * jp],     ah, bl[4 * jp],     bl[4 * jp + 1]);
            mma_bf16(acc[2 * jp + 1], ah, bl[4 * jp + 2], bl[4 * jp + 3]);
        }
#pragma unroll
        for (int jp = 0; jp < 4; jp++) {      // lo * hi
            mma_bf16(acc[2 * jp],     al, bh[4 * jp],     bh[4 * jp + 1]);
            mma_bf16(acc[2 * jp + 1], al, bh[4 * jp + 2], bh[4 * jp + 3]);
        }
    }
}

// ---------------------------------------------------------------------------
// Warp-local hidden epilogue: 16-col chunks through per-warp scratch
// (stride 18 floats, conflict-light), tanh chain, write own A rows/cols.
// Only __syncwarp inside; zero cross-warp sync.
// ---------------------------------------------------------------------------
__device__ __forceinline__ void epi_hidden_warp(char* sm, float* S,
                                                const float* __restrict__ b,
                                                int lane, int wm, int wn,
                                                const float acc[8][4])
{
    const int g  = lane >> 2, q = lane & 3;
    const int p4 = lane >> 3;            // local point 0..3
    const int cl = 2 * (lane & 7);       // local col within chunk 0..14

#pragma unroll
    for (int ch2 = 0; ch2 < 4; ch2++) {
        // ---- store this chunk (16 cols) of the fragment ----
#pragma unroll
        for (int t = 0; t < 2; t++) {
            const int nt = 2 * ch2 + t;
            const int cb = t * 8 + 2 * q;
            *(float2*)&S[g * 18 + cb]       = make_float2(acc[nt][0], acc[nt][1]);
            *(float2*)&S[(g + 8) * 18 + cb] = make_float2(acc[nt][2], acc[nt][3]);
        }
        __syncwarp();

        // ---- transposed read: 4 channels x 2 cols for (p4, cl) ----
        float d[4][2];
#pragma unroll
        for (int c = 0; c < 4; c++)
            *(float2*)&d[c][0] = *(const float2*)&S[(4 * p4 + c) * 18 + cl];

        const int colg = wn * 64 + ch2 * 16 + cl;
        float o[4][2];
#pragma unroll
        for (int i = 0; i < 2; i++) {
            float a  = my_tanh(d[0][i] + __ldg(&b[colg + i]));
            float t1 = 1.0f - a * a;
            float t2 = -2.0f * a * t1;
            o[0][i] = a;
            o[1][i] = t1 * d[1][i];
            o[2][i] = t1 * d[2][i];
            o[3][i] = fmaf(t2, fmaf(d[1][i], d[1][i], d[2][i] * d[2][i]),
                           t1 * d[3][i]);
        }

        // ---- write A hi/lo (own rows, own col half) ----
#pragma unroll
        for (int c = 0; c < 4; c++) {
            const int row = wm * 16 + 4 * p4 + c;
            float h0 = __bfloat162float(__float2bfloat16(o[c][0]));
            float h1 = __bfloat162float(__float2bfloat16(o[c][1]));
            u32 off = toff(row, colg);
            *(u32*)(sm + SM_AHI + off) = pack2bf(o[c][0], o[c][1]);
            *(u32*)(sm + SM_ALO + off) = pack2bf(o[c][0] - h0, o[c][1] - h1);
        }
        __syncwarp();
    }
}

// ---------------------------------------------------------------------------
// Warp-local output epilogue: partial lap over this warp's 64 cols for its
// 4 points. Returns per-lane partial; reduce over 8-lane groups afterwards.
// ---------------------------------------------------------------------------
__device__ __forceinline__ float epi_out_warp(float* S,
                                              const float* __restrict__ b2,
                                              const float* __restrict__ W3,
                                              int lane, int wn,
                                              const float acc[8][4])
{
    const int g  = lane >> 2, q = lane & 3;
    const int p4 = lane >> 3;
    const int cl = 2 * (lane & 7);

    float s = 0.0f;
#pragma unroll
    for (int ch2 = 0; ch2 < 4; ch2++) {
#pragma unroll
        for (int t = 0; t < 2; t++) {
            const int nt = 2 * ch2 + t;
            const int cb = t * 8 + 2 * q;
            *(float2*)&S[g * 18 + cb]       = make_float2(acc[nt][0], acc[nt][1]);
            *(float2*)&S[(g + 8) * 18 + cb] = make_float2(acc[nt][2], acc[nt][3]);
        }
        __syncwarp();

        float d[4][2];
#pragma unroll
        for (int c = 0; c < 4; c++)
            *(float2*)&d[c][0] = *(const float2*)&S[(4 * p4 + c) * 18 + cl];

        const int colg = wn * 64 + ch2 * 16 + cl;
#pragma unroll
        for (int i = 0; i < 2; i++) {
            float a  = my_tanh(d[0][i] + __ldg(&b2[colg + i]));
            float t1 = 1.0f - a * a;
            float t2 = -2.0f * a * t1;
            float L  = fmaf(t2, fmaf(d[1][i], d[1][i], d[2][i] * d[2][i]),
                            t1 * d[3][i]);
            s = fmaf(L, __ldg(&W3[colg + i]), s);
        }
        __syncwarp();
    }
    return s;
}

// ---------------------------------------------------------------------------
// Interior: HMMA bf16-split Taylor-mode Laplacian. Persistent CTAs,
// 16 warps as 8 independent warp-PAIRS (pair wm = warps {wm, 8+wm}).
// All tile-loop sync is pair-scoped (named barriers) or warp-local.
// GEMM rows: r = p*4 + c (p = point 0..31; c = v, gx, gy, L).
// ---------------------------------------------------------------------------
__global__ __launch_bounds__(THREADS_I, 1)
void pinn_interior(const float* __restrict__ xy, const float* __restrict__ f,
                   const float* __restrict__ W0, const float* __restrict__ b0,
                   const float* __restrict__ W1, const float* __restrict__ b1,
                   const float* __restrict__ W2, const float* __restrict__ b2,
                   const float* __restrict__ W3, int n, int ntiles)
{
    extern __shared__ __align__(128) char sm[];
    const u32 smb = smem_to_u32(sm);

    const int tid  = threadIdx.x;
    const int wid  = tid >> 5;
    const int lane = tid & 31;
    const int wm   = wid & 7;       // pair id
    const int wn   = wid >> 3;      // half id within pair
    const int bid  = wm + 1;        // named barrier id (1..8)

    float* S    = (float*)(sm + SM_TS + wid * TS_WARP);
    float* SLAP = (float*)(sm + SM_SLAP);

    // ---- one-time: split + transpose W1/W2 into bf16 hi/lo B^T tiles ----
    for (int idx = tid; idx < H * H; idx += THREADS_I) {
        int k = idx >> 7, nn = idx & 127;     // W[k][nn], coalesced over nn
        u32 off = toff(nn, k);                // B^T cell (row=n, col=k)
        float w1 = W1[idx], w2 = W2[idx];
        __nv_bfloat16 h1 = __float2bfloat16(w1);
        __nv_bfloat16 h2 = __float2bfloat16(w2);
        *(__nv_bfloat16*)(sm + SM_W1HI + off) = h1;
        *(__nv_bfloat16*)(sm + SM_W1LO + off) = __float2bfloat16(w1 - __bfloat162float(h1));
        *(__nv_bfloat16*)(sm + SM_W2HI + off) = h2;
        *(__nv_bfloat16*)(sm + SM_W2LO + off) = __float2bfloat16(w2 - __bfloat162float(h2));
    }
    __syncthreads();   // only block-wide sync; weights static afterwards

    for (int tile = blockIdx.x; tile < ntiles; tile += gridDim.x) {
        const int base = tile * PTS;

        // ---- layer 0 seed: pair wm seeds its own 4 points (rows 16wm..) ----
        {
            const int tp = wn * 32 + lane;    // 0..63 within pair
#pragma unroll
            for (int r = 0; r < 2; r++) {
                int it = tp * 2 + r;          // 0..127
                int pl = it >> 5;             // local point 0..3
                int j0 = (it & 31) * 4;
                int pt = base + wm * 4 + pl; if (pt > n - 1) pt = n - 1;
                float x = __ldg(&xy[pt * 2 + 0]);
                float y = __ldg(&xy[pt * 2 + 1]);
                float o[4][4];   // [unit][channel]
#pragma unroll
                for (int jj = 0; jj < 4; jj++) {
                    int j = j0 + jj;
                    float wx = __ldg(&W0[j]), wy = __ldg(&W0[H + j]);
                    float zv = fmaf(x, wx, fmaf(y, wy, __ldg(&b0[j])));
                    float a  = my_tanh(zv);
                    float t1 = 1.0f - a * a;
                    float t2 = -2.0f * a * t1;
                    o[jj][0] = a;
                    o[jj][1] = t1 * wx;
                    o[jj][2] = t1 * wy;
                    o[jj][3] = t2 * fmaf(wx, wx, wy * wy);
                }
#pragma unroll
                for (int c = 0; c < 4; c++) {
                    int row = wm * 16 + pl * 4 + c;
                    u32 off = toff(row, j0);
                    float v0 = o[0][c], v1 = o[1][c], v2 = o[2][c], v3 = o[3][c];
                    float h0 = __bfloat162float(__float2bfloat16(v0));
                    float h1 = __bfloat162float(__float2bfloat16(v1));
                    float h2 = __bfloat162float(__float2bfloat16(v2));
                    float h3 = __bfloat162float(__float2bfloat16(v3));
                    *(uint2*)(sm + SM_AHI + off) =
                        make_uint2(pack2bf(v0, v1), pack2bf(v2, v3));
                    *(uint2*)(sm + SM_ALO + off) =
                        make_uint2(pack2bf(v0 - h0, v1 - h1),
                                   pack2bf(v2 - h2, v3 - h3));
                }
            }
        }
        PBAR(bid);   // pair's A rows seeded (both halves)

        float acc[8][4];

        // ---- layer 1: mainloop + warp-local epilogue ----
        mainloop(smb, SM_AHI, SM_ALO, SM_W1HI, SM_W1LO, lane, wm, wn, acc);
        epi_hidden_warp(sm, S, b1, lane, wm, wn, acc);
        PBAR(bid);   // pair's new A rows complete (both col halves)

        // ---- layer 2 + output projection ----
        mainloop(smb, SM_AHI, SM_ALO, SM_W2HI, SM_W2LO, lane, wm, wn, acc);
        float s = epi_out_warp(S, b2, W3, lane, wn, acc);

        // reduce over the 8 col-lanes of each local point
        s += __shfl_xor_sync(0xffffffffu, s, 1);
        s += __shfl_xor_sync(0xffffffffu, s, 2);
        s += __shfl_xor_sync(0xffffffffu, s, 4);
        if ((lane & 7) == 0)
            SLAP[(wm * 4 + (lane >> 3)) * 2 + wn] = s;
        PBAR(bid);   // both halves' partial laps visible to pair

        if (wn == 0 && lane < 4) {
            int idx = base + wm * 4 + lane;
            float d = 0.0f;
            if (idx < n) {
                float lap = SLAP[(wm * 4 + lane) * 2]
                          + SLAP[(wm * 4 + lane) * 2 + 1];
                d = lap - f[idx];
            }
            float v = d * d;
            v += __shfl_xor_sync(0x0000000fu, v, 1);
            v += __shfl_xor_sync(0x0000000fu, v, 2);
            if (lane == 0) g_part_int[tile * 8 + wm] = v;
        }
        PBAR(bid);   // SLAP consumed; safe for next tile
    }
}

// ---------------------------------------------------------------------------
// Boundary: plain fp32 forward + squared residual (small workload, unchanged).
// ---------------------------------------------------------------------------
__device__ __forceinline__ void hidden1(const float* __restrict__ in,
                                        float* __restrict__ outp,
                                        const float* __restrict__ W,
                                        const float* __restrict__ b,
                                        int j, int p0)
{
    float acc[TB / 2];
#pragma unroll
    for (int p = 0; p < TB / 2; p++) acc[p] = 0.0f;

#pragma unroll 1
    for (int k = 0; k < H; k += 4) {
        const float w0 = W[(k + 0) * H + j];
        const float w1 = W[(k + 1) * H + j];
        const float w2 = W[(k + 2) * H + j];
        const float w3 = W[(k + 3) * H + j];
#pragma unroll
        for (int p = 0; p < TB / 2; p++) {
            const float4 a = *reinterpret_cast<const float4*>(&in[(p0 + p) * H + k]);
            acc[p] = fmaf(a.x, w0, fmaf(a.y, w1, fmaf(a.z, w2, fmaf(a.w, w3, acc[p]))));
        }
    }
    const float bj = b[j];
#pragma unroll
    for (int p = 0; p < TB / 2; p++)
        outp[(p0 + p) * H + j] = my_tanh(acc[p] + bj);
}

__global__ __launch_bounds__(THREADS)
void pinn_boundary(const float* __restrict__ xy, const float* __restrict__ g,
                   const float* __restrict__ W0, const float* __restrict__ b0,
                   const float* __restrict__ W1, const float* __restrict__ b1,
                   const float* __restrict__ W2, const float* __restrict__ b2,
                   const float* __restrict__ W3, const float* __restrict__ b3,
                   int n)
{
    __shared__ __align__(16) float A[TB * H];
    __shared__ __align__(16) float B[TB * H];
    __shared__ float sxy[TB * 2];
    __shared__ float red[TB];

    const int tid  = threadIdx.x;
    const int j    = tid & (H - 1);
    const int p0   = (tid >> 7) * (TB / 2);
    const int base = blockIdx.x * TB;

    if (tid < TB * 2) {
        int pt = base + (tid >> 1);
        if (pt > n - 1) pt = n - 1;
        sxy[tid] = xy[pt * 2 + (tid & 1)];
    }
    __syncthreads();

    {
        const float w0x = W0[j], w0y = W0[H + j], bj = b0[j];
#pragma unroll
        for (int p = 0; p < TB / 2; p++) {
            const int pp = p0 + p;
            A[pp * H + j] = my_tanh(fmaf(sxy[pp * 2], w0x, fmaf(sxy[pp * 2 + 1], w0y, bj)));
        }
    }
    __syncthreads();
    hidden1(A, B, W1, b1, j, p0);
    __syncthreads();
    hidden1(B, A, W2, b2, j, p0);
    __syncthreads();

    if (tid < TB) {
        float v = b3[0];
        for (int k = 0; k < H; k++) v = fmaf(A[tid * H + k], W3[k], v);
        int idx = base + tid;
        if (idx < n) { float d = v - g[idx]; red[tid] = d * d; }
        else red[tid] = 0.0f;
    }
    __syncthreads();

    if (tid == 0) {
        float s = 0.0f;
#pragma unroll
        for (int p = 0; p < TB; p++) s += red[p];
        g_part_bd[blockIdx.x] = s;
    }
}

// ---------------------------------------------------------------------------
__global__ __launch_bounds__(THREADS)
void pinn_finalize(float* __restrict__ out, int nbi, int nbb, int n_int, int n_bd)
{
    __shared__ float s[THREADS];
    const int tid = threadIdx.x;

    float a = 0.0f;
    for (int i = tid; i < nbi; i += THREADS) a += g_part_int[i];
    s[tid] = a;
    __syncthreads();
    for (int st = THREADS / 2; st > 0; st >>= 1) {
        if (tid < st) s[tid] += s[tid + st];
        __syncthreads();
    }
    float loss_f = 0.0f;
    if (tid == 0) loss_f = s[0] * (0.5f / (float)n_int);
    __syncthreads();

    float bsm = 0.0f;
    for (int i = tid; i < nbb; i += THREADS) bsm += g_part_bd[i];
    s[tid] = bsm;
    __syncthreads();
    for (int st = THREADS / 2; st > 0; st >>= 1) {
        if (tid < st) s[tid] += s[tid + st];
        __syncthreads();
    }
    if (tid == 0) {
        out[0] = s[0] * (0.5f / (float)n_bd);
        out[1] = loss_f;
    }
}

// ---------------------------------------------------------------------------
extern "C" void kernel_launch(void* const* d_in, const int* in_sizes, int n_in,
                              void* d_out, int out_size)
{
    const float* xy_int = (const float*)d_in[0];
    const float* f      = (const float*)d_in[1];
    const float* xy_bd  = (const float*)d_in[2];
    const float* g      = (const float*)d_in[3];
    const float* W0     = (const float*)d_in[4];
    const float* b0     = (const float*)d_in[5];
    const float* W1     = (const float*)d_in[6];
    const float* b1     = (const float*)d_in[7];
    const float* W2     = (const float*)d_in[8];
    const float* b2     = (const float*)d_in[9];
    const float* W3     = (const float*)d_in[10];
    const float* b3     = (const float*)d_in[11];

    const int n_int = in_sizes[0] / 2;
    const int n_bd  = in_sizes[2] / 2;

    int ntiles = (n_int + PTS - 1) / PTS;
    if (ntiles > 8192) ntiles = 8192;     // scratch bound: ntiles*8 <= 65536
    int gb = (n_bd + TB - 1) / TB;
    if (gb > 8192) gb = 8192;             // scratch bound (dataset: 512)

    int gi = NBLK < ntiles ? NBLK : ntiles;

    cudaFuncSetAttribute(pinn_interior,
                         cudaFuncAttributeMaxDynamicSharedMemorySize, SMEM_TOTAL);

    pinn_interior<<<gi, THREADS_I, SMEM_TOTAL>>>(xy_int, f, W0, b0, W1, b1,
                                                 W2, b2, W3, n_int, ntiles);
    pinn_boundary<<<gb, THREADS>>>(xy_bd, g, W0, b0, W1, b1, W2, b2, W3, b3, n_bd);
    pinn_finalize<<<1, THREADS>>>((float*)d_out, ntiles * 8, gb, n_int, n_bd);
}